// round 12
// baseline (speedup 1.0000x reference)
#include <cuda_runtime.h>
#include <cuda_fp16.h>
#include <cstdint>

// Problem constants
#define Bq   1024
#define Nn   128
#define Dd   256
#define Hh   8
#define NB   2
#define NEGV (-1e9f)
#define CLIPV 10.0f
#define INV_SQRT_DH 0.17677669529663687f  // 1/sqrt(32)
#define INV_SQRT_D  0.0625f               // 1/sqrt(256)

#define ROWS_TOTAL (Bq * Nn)              // 131072
#define WSCALE     16.0f                  // W pre-scale (exact pow2)
#define WUNSCALE   0.0625f                // 1/16

// ---------------- scratch (device globals; no cudaMalloc allowed) ----------
__device__ float g_K   [Bq * Nn * Dd];   // [b][n][d]  (E@Wk)
__device__ float g_V   [Bq * Nn * Dd];   // [b][n][d]  (E@Wv)
__device__ float g_LK2 [Bq * Nn * Dd];   // [b][n][d]  (E@(Wlk@Wo^T))
__device__ float g_P   [Bq * Nn * Dd];   // [b][n][d]  (E@Ws_bot)
__device__ float g_q0  [Bq * Dd];        // step-0 query (pre-MLP)
__device__ float g_Woc [Dd * Dd];        // Wo@Wc
__device__ float g_Wlk2[Dd * Dd];        // Wlk@Wo^T
__device__ float g_WoT [Dd * Dd];        // Wo^T
__device__ float g_pc  [Dd];             // W_placeholder @ Ws
__device__ int   g_mlp;                  // 1 if (W2,b2) nonzero -> general path

// fp16 2-way splits (x ~= h0+h1 to ~2^-22)
__device__ __half g_Es[2][ROWS_TOTAL * Dd];     // E splits
__device__ __half g_Wt[2][4][Dd * Dd];          // (16*W)^T splits [s][w][n][k]

// ================= helpers ==================================================
__device__ __forceinline__ uint32_t smem_u32(const void* p) {
    uint32_t a;
    asm("{ .reg .u64 t; cvta.to.shared.u64 t, %1; cvt.u32.u64 %0, t; }"
        : "=r"(a) : "l"(p));
    return a;
}
__device__ __forceinline__ void ldsm_x4(uint32_t* r, uint32_t addr) {
    asm volatile("ldmatrix.sync.aligned.m8n8.x4.shared.b16 {%0,%1,%2,%3}, [%4];"
        : "=r"(r[0]), "=r"(r[1]), "=r"(r[2]), "=r"(r[3]) : "r"(addr));
}
__device__ __forceinline__ void mma_fp16(float* c, const uint32_t* a, const uint32_t* b) {
    asm volatile("mma.sync.aligned.m16n8k16.row.col.f32.f16.f16.f32 "
        "{%0,%1,%2,%3}, {%4,%5,%6,%7}, {%8,%9}, {%0,%1,%2,%3};"
        : "+f"(c[0]), "+f"(c[1]), "+f"(c[2]), "+f"(c[3])
        : "r"(a[0]), "r"(a[1]), "r"(a[2]), "r"(a[3]), "r"(b[0]), "r"(b[1]));
}
__device__ __forceinline__ void cp_async16(uint32_t dst, const void* src) {
    asm volatile("cp.async.cg.shared.global [%0], [%1], 16;"
                 :: "r"(dst), "l"(src) : "memory");
}
#define CP_COMMIT() asm volatile("cp.async.commit_group;" ::: "memory")
#define CP_WAIT0()  asm volatile("cp.async.wait_group 0;" ::: "memory")

// buffer offsets (macros: device-safe)
#define K3_ABUF(p) ((p) * 16384)
#define K3_BBUF(p) (32768 + (p) * 16384)
#define K3T_SMEM   65536

// ---------------- k0: transpose Wo, detect MLP-nonzero ---------------------
__global__ void k0_prep(const float* __restrict__ Wo,
                        const float* __restrict__ W2,
                        const float* __restrict__ b2)
{
    if (blockIdx.x == 0) {
        for (int i = threadIdx.x; i < Dd * Dd; i += blockDim.x) {
            int k = i >> 8, d = i & 255;
            g_WoT[d * Dd + k] = Wo[k * Dd + d];
        }
    } else {
        __shared__ int any;
        if (threadIdx.x == 0) any = 0;
        __syncthreads();
        int loc = 0;
        for (int i = threadIdx.x; i < Dd * Dd; i += blockDim.x)
            loc |= (W2[i] != 0.0f);
        if (threadIdx.x < Dd) loc |= (b2[threadIdx.x] != 0.0f);
        if (loc) atomicOr(&any, 1);
        __syncthreads();
        if (threadIdx.x == 0) g_mlp = any;
    }
}

// ---------------- k1: Woc = Wo@Wc ; Wlk2 = Wlk@Wo^T ; pc = placeholder@Ws --
__global__ void k1_weights(const float* __restrict__ Wo,
                           const float* __restrict__ Wc,
                           const float* __restrict__ Wlk,
                           const float* __restrict__ Ws,
                           const float* __restrict__ Wph)
{
    int bid = blockIdx.x;
    int d = threadIdx.x;
    if (bid < 256) {
        float acc = 0.f;
        #pragma unroll 8
        for (int j = 0; j < Dd; j++) acc += Wo[bid * Dd + j] * Wc[j * Dd + d];
        g_Woc[bid * Dd + d] = acc;
    } else if (bid < 512) {
        int m = bid - 256;
        float acc = 0.f;
        #pragma unroll 8
        for (int j = 0; j < Dd; j++) acc += Wlk[m * Dd + j] * g_WoT[j * Dd + d];
        g_Wlk2[m * Dd + d] = acc;
    } else {
        float acc = 0.f;
        #pragma unroll 8
        for (int k = 0; k < 2 * Dd; k++) acc += Wph[k] * Ws[k * Dd + d];
        g_pc[d] = acc;
    }
}

// ---------------- k2: q0 = mean_n(E) @ Wc + pc ------------------------------
__global__ void k2_q0(const float* __restrict__ E, const float* __restrict__ Wc)
{
    int b = blockIdx.x, d = threadIdx.x;
    __shared__ float g[Dd];
    float s = 0.f;
    const float* Eb = E + (size_t)b * Nn * Dd + d;
    #pragma unroll 8
    for (int n = 0; n < Nn; n++) s += Eb[n * Dd];
    g[d] = s * (1.0f / Nn);
    __syncthreads();
    float acc = g_pc[d];
    #pragma unroll 8
    for (int k = 0; k < Dd; k++) acc += g[k] * Wc[k * Dd + d];
    g_q0[b * Dd + d] = acc;
}

// ---------------- split kernels: fp32 -> 2x fp16 (to ~2^-22) ----------------
__global__ void k_splitE(const float* __restrict__ E)
{
    const size_t total = (size_t)ROWS_TOTAL * Dd;
    const size_t stride = (size_t)gridDim.x * blockDim.x;
    for (size_t i = (size_t)blockIdx.x * blockDim.x + threadIdx.x; i < total; i += stride) {
        float x = E[i];
        __half h0 = __float2half_rn(x);
        float r = x - __half2float(h0);
        __half h1 = __float2half_rn(r);
        g_Es[0][i] = h0; g_Es[1][i] = h1;
    }
}

// transposed weight splits of 16*W: g_Wt[s][w][n*256+k] = split_s(16 * W_w[k][n])
__global__ void k_splitW(const float* __restrict__ Wk,
                         const float* __restrict__ Wv,
                         const float* __restrict__ Ws)
{
    const int w = blockIdx.x, n = blockIdx.y, k = threadIdx.x;
    const float* src;
    if      (w == 0) src = Wk;
    else if (w == 1) src = Wv;
    else if (w == 2) src = g_Wlk2;
    else             src = Ws + Dd * Dd;
    float x = src[k * Dd + n] * WSCALE;
    __half h0 = __float2half_rn(x);
    float r = x - __half2float(h0);
    __half h1 = __float2half_rn(r);
    g_Wt[0][w][n * Dd + k] = h0;
    g_Wt[1][w][n * Dd + k] = h1;
}

// ---------------- k3t: mma.sync fp16-2split GEMM, cp.async pipelined --------
// CTA tile 128m x 128n, 8 warps (each 32m x 64n). K chunked x32, 8 chunks,
// double-buffered cp.async staging (stage c+1 overlaps compute c).
// Buffers: A[2]:16KB + B[2]:16KB = 64KB -> 2 CTAs/SM. 64B rows, SW64 swizzle.
// 3 split passes (00, 01, 10); output unscaled by 1/16.
__global__ void __launch_bounds__(256, 2) k3t_mma()
{
    extern __shared__ char smem[];
    const uint32_t sbase = smem_u32(smem);
    const int tid = threadIdx.x;
    const int warp = tid >> 5, lane = tid & 31;
    const int rowbase = blockIdx.x * 128;
    const int nbase   = blockIdx.y * 128;
    const int w       = blockIdx.z;

    float* out;
    if      (w == 0) out = g_K;
    else if (w == 1) out = g_V;
    else if (w == 2) out = g_LK2;
    else             out = g_P;

    const int wm = warp & 3;      // 4 m-blocks of 32 rows
    const int wn = warp >> 2;     // 2 n-blocks of 64 cols

    float acc[2][8][4] = {};      // [mblk16][nblk8][frag]

    // Staging decode for this thread (2048 16B copies per chunk, 8 per thread).
    uint32_t st_dst[8];           // buffer-relative dst offsets
    const __half* st_src[8];      // chunk-0 src pointers (advance by 32/chunk)
    #pragma unroll
    for (int it = 0; it < 8; it++) {
        int i = tid + it * 256;
        int reg = i >> 10, s = (i >> 9) & 1, row = (i >> 2) & 127, q = i & 3;
        uint32_t off = (uint32_t)(s * 8192 + row * 64 + ((q * 16) ^ ((row & 6) << 3)));
        if (reg == 0) {
            st_dst[it] = off;                     // relative to ABUF(p)
            st_src[it] = &g_Es[s][(size_t)(rowbase + row) * Dd + q * 8];
        } else {
            st_dst[it] = 32768u + off;            // relative to ABUF(p) -> BBUF(p)
            st_src[it] = &g_Wt[s][w][(size_t)(nbase + row) * Dd + q * 8];
        }
    }

    // Hoisted ldmatrix addressing (64B pitch, SW64):
    uint32_t a_off[2], a_mask[2];
    #pragma unroll
    for (int mb = 0; mb < 2; mb++) {
        int row = wm * 32 + mb * 16 + (lane & 15);
        a_off[mb]  = (uint32_t)(row * 64);
        a_mask[mb] = (uint32_t)(((row & 6) << 3) ^ ((lane >> 4) * 16));
    }
    uint32_t b_off[4], b_mask[4];
    #pragma unroll
    for (int p = 0; p < 4; p++) {
        int pr = lane >> 3;
        int nrow = wn * 64 + p * 16 + ((pr >> 1) << 3) + (lane & 7);
        b_off[p]  = (uint32_t)(nrow * 64);
        b_mask[p] = (uint32_t)(((nrow & 6) << 3) ^ ((pr & 1) * 16));
    }

    // prologue: stage chunk 0 into buffer 0
    {
        const uint32_t abase = sbase + K3_ABUF(0);
        #pragma unroll
        for (int it = 0; it < 8; it++)
            cp_async16(abase + st_dst[it], st_src[it]);
        CP_COMMIT();
    }

    for (int c = 0; c < 8; c++) {
        CP_WAIT0();
        __syncthreads();

        if (c + 1 < 8) {   // stage next chunk into the other buffer
            const uint32_t abase = sbase + K3_ABUF((c + 1) & 1);
            const int kadv = (c + 1) * 32;
            #pragma unroll
            for (int it = 0; it < 8; it++)
                cp_async16(abase + st_dst[it], st_src[it] + kadv);
            CP_COMMIT();
        }

        const uint32_t Ab = sbase + K3_ABUF(c & 1);
        const uint32_t Bb = sbase + K3_BBUF(c & 1);

        #pragma unroll
        for (int ks = 0; ks < 2; ks++) {
            const uint32_t kx = (uint32_t)(ks * 32);
            uint32_t af[2][2][4];    // [split][mblk][frag]
            #pragma unroll
            for (int s = 0; s < 2; s++)
                #pragma unroll
                for (int mb = 0; mb < 2; mb++)
                    ldsm_x4(af[s][mb], Ab + s * 8192 + a_off[mb] + (kx ^ a_mask[mb]));
            #pragma unroll
            for (int p = 0; p < 4; p++) {
                uint32_t b0[4];
                ldsm_x4(b0, Bb + b_off[p] + (kx ^ b_mask[p]));           // split 0
                #pragma unroll
                for (int sa = 0; sa < 2; sa++) {
                    mma_fp16(acc[0][2 * p],     af[sa][0], b0 + 0);
                    mma_fp16(acc[0][2 * p + 1], af[sa][0], b0 + 2);
                    mma_fp16(acc[1][2 * p],     af[sa][1], b0 + 0);
                    mma_fp16(acc[1][2 * p + 1], af[sa][1], b0 + 2);
                }
                uint32_t b1[4];
                ldsm_x4(b1, Bb + 8192 + b_off[p] + (kx ^ b_mask[p]));    // split 1
                mma_fp16(acc[0][2 * p],     af[0][0], b1 + 0);
                mma_fp16(acc[0][2 * p + 1], af[0][0], b1 + 2);
                mma_fp16(acc[1][2 * p],     af[0][1], b1 + 0);
                mma_fp16(acc[1][2 * p + 1], af[0][1], b1 + 2);
            }
        }
        __syncthreads();
    }

    // ---- epilogue: unscale by 1/16 (exact), fp32 stores --------------------
    const int r0 = rowbase + wm * 32 + (lane >> 2);
    const int c0 = nbase + wn * 64 + (lane & 3) * 2;
    #pragma unroll
    for (int mb = 0; mb < 2; mb++)
        #pragma unroll
        for (int nb = 0; nb < 8; nb++) {
            float2 lo = make_float2(acc[mb][nb][0] * WUNSCALE, acc[mb][nb][1] * WUNSCALE);
            float2 hi = make_float2(acc[mb][nb][2] * WUNSCALE, acc[mb][nb][3] * WUNSCALE);
            *(float2*)(out + (size_t)(r0 + mb * 16)     * Dd + c0 + nb * 8) = lo;
            *(float2*)(out + (size_t)(r0 + mb * 16 + 8) * Dd + c0 + nb * 8) = hi;
        }
}

// ---------------- k4: persistent decode, NB=2 batches per block -------------
struct K4Smem {
    float q[NB][Dd];
    float heads[NB][Dd];
    float cc[NB][Nn][9];
    float pp[NB][Hh][Nn + 4];
    float ls[NB][Nn];
    int   list[NB][Nn];
    float er[NB][Dd];
    float sum[NB][Hh];
    int   sel[NB];
    int   cnt;
};

__device__ __forceinline__ void k4_finalize_q(K4Smem& S, int tid, int mlp,
                                              const float* __restrict__ W1,
                                              const float* __restrict__ b1,
                                              const float* __restrict__ W2,
                                              const float* __restrict__ b2)
{
    if (mlp) {
        __syncthreads();
        float m1[NB];
        #pragma unroll
        for (int bb = 0; bb < NB; bb++) m1[bb] = b1[tid];
        #pragma unroll 8
        for (int k = 0; k < Dd; k++) {
            float wv = W1[k * Dd + tid];
            #pragma unroll
            for (int bb = 0; bb < NB; bb++) m1[bb] += S.q[bb][k] * wv;
        }
        #pragma unroll
        for (int bb = 0; bb < NB; bb++) S.er[bb][tid] = fmaxf(m1[bb], 0.0f);
        __syncthreads();
        float m2[NB];
        #pragma unroll
        for (int bb = 0; bb < NB; bb++) m2[bb] = b2[tid];
        #pragma unroll 8
        for (int k = 0; k < Dd; k++) {
            float wv = W2[k * Dd + tid];
            #pragma unroll
            for (int bb = 0; bb < NB; bb++) m2[bb] += S.er[bb][k] * wv;
        }
        __syncthreads();
        #pragma unroll
        for (int bb = 0; bb < NB; bb++)
            S.q[bb][tid] = (S.q[bb][tid] + m2[bb]) * INV_SQRT_DH;
    } else {
        #pragma unroll
        for (int bb = 0; bb < NB; bb++) S.q[bb][tid] *= INV_SQRT_DH;
    }
    __syncthreads();
}

__global__ void __launch_bounds__(256, 4) k4_decode(const float* __restrict__ E,
                                                    const float* __restrict__ coords,
                                                    const float* __restrict__ Ws,
                                                    const float* __restrict__ W1,
                                                    const float* __restrict__ b1,
                                                    const float* __restrict__ W2,
                                                    const float* __restrict__ b2,
                                                    float* __restrict__ out)
{
    extern __shared__ char smem_raw[];
    K4Smem& S = *(K4Smem*)smem_raw;

    const int b0 = blockIdx.x * NB;
    const int tid = threadIdx.x;
    const int warp = tid >> 5, lane = tid & 31;
    const int wb  = warp >> 2;
    const int wj0 = warp & 3;
    const int mlp = g_mlp;

    if (tid < Nn) {
        #pragma unroll
        for (int bb = 0; bb < NB; bb++) S.list[bb][tid] = tid;
    }
    if (tid == 0) S.cnt = Nn;
    #pragma unroll
    for (int bb = 0; bb < NB; bb++)
        S.q[bb][tid] = g_q0[(b0 + bb) * Dd + tid];
    k4_finalize_q(S, tid, mlp, W1, b1, W2, b2);

    const float* Kbase  = g_K   + (size_t)b0 * Nn * Dd;
    const float* Vbase  = g_V   + (size_t)b0 * Nn * Dd;
    const float* LKbase = g_LK2 + (size_t)b0 * Nn * Dd;

    float ll = 0.f, cost = 0.f;
    float fx = 0.f, fy = 0.f, px = 0.f, py = 0.f;
    float fctx[NB] = {0.f, 0.f};

    for (int t = 0; t < Nn; t++) {
        const int cnt = S.cnt;

        {   // ---- compat ----
            const float4* q4 = (const float4*)S.q[wb];
            float4 qa = q4[lane], qb = q4[lane + 32];
            const float* Kb = Kbase + (size_t)wb * Nn * Dd;
            const int* lst = S.list[wb];
            for (int j = wj0; j < cnt; j += 4) {
                const float4* Kr = (const float4*)(Kb + (size_t)lst[j] * Dd);
                float4 k0 = __ldcg(Kr + lane);
                float4 k1 = __ldcg(Kr + lane + 32);
                float alo = k0.x * qa.x + k0.y * qa.y + k0.z * qa.z + k0.w * qa.w;
                float ahi = k1.x * qb.x + k1.y * qb.y + k1.z * qb.z + k1.w * qb.w;
                #pragma unroll
                for (int o = 1; o < 8; o <<= 1) {
                    alo += __shfl_xor_sync(0xffffffffu, alo, o);
                    ahi += __shfl_xor_sync(0xffffffffu, ahi, o);
                }
                if ((lane & 7) == 0) {
                    int hg = lane >> 3;
                    S.cc[wb][j][hg]     = alo;
                    S.cc[wb][j][4 + hg] = ahi;
                }
            }
        }
        __syncthreads();

        {   // ---- softmax ----
            const int h = warp;
            #pragma unroll
            for (int bb = 0; bb < NB; bb++) {
                float m = NEGV;
                for (int j = lane; j < cnt; j += 32) m = fmaxf(m, S.cc[bb][j][h]);
                #pragma unroll
                for (int o = 16; o; o >>= 1)
                    m = fmaxf(m, __shfl_xor_sync(0xffffffffu, m, o));
                float s = 0.f;
                for (int j = lane; j < cnt; j += 32) {
                    float e = expf(S.cc[bb][j][h] - m);
                    S.pp[bb][h][j] = e;
                    s += e;
                }
                #pragma unroll
                for (int o = 16; o; o >>= 1) s += __shfl_xor_sync(0xffffffffu, s, o);
                if (lane == 0) S.sum[bb][h] = s;
            }
        }
        __syncthreads();

        {   // ---- heads ----
            const int d = tid, h = tid >> 5;
            float a[NB] = {0.f, 0.f};
            const float* Vd = Vbase + d;
            #pragma unroll 2
            for (int j = 0; j < cnt; j++) {
                #pragma unroll
                for (int bb = 0; bb < NB; bb++)
                    a[bb] += S.pp[bb][h][j] *
                             __ldcg(Vd + ((size_t)bb * Nn + S.list[bb][j]) * Dd);
            }
            #pragma unroll
            for (int bb = 0; bb < NB; bb++)
                S.heads[bb][d] = a[bb] / S.sum[bb][h];
        }
        __syncthreads();

        // ---- Woc matvec hoisted BEFORE logits: overlaps its L2 traffic
        //      with the logits/argmax phases (result kept in registers) ----
        float mv0 = 0.f, mv1 = 0.f;
        if (t < Nn - 1) {
            float a0 = 0.f, a1 = 0.f, b0a = 0.f, b1a = 0.f;
            const float* Wp = g_Woc + tid;
            #pragma unroll 8
            for (int k = 0; k < Dd; k += 2) {
                float wv0 = Wp[(size_t)k * Dd];
                float wv1 = Wp[(size_t)(k + 1) * Dd];
                a0  += S.heads[0][k]     * wv0;
                b0a += S.heads[1][k]     * wv0;
                a1  += S.heads[0][k + 1] * wv1;
                b1a += S.heads[1][k + 1] * wv1;
            }
            mv0 = a0 + a1;
            mv1 = b0a + b1a;
        }

        {   // ---- logits ----
            const float4* h4 = (const float4*)S.heads[wb];
            float4 ha = h4[lane], hb = h4[lane + 32];
            const float* Lb = LKbase + (size_t)wb * Nn * Dd;
            const int* lst = S.list[wb];
            for (int j = wj0; j < cnt; j += 4) {
                const float4* Lr = (const float4*)(Lb + (size_t)lst[j] * Dd);
                float4 l0 = __ldcg(Lr + lane);
                float4 l1 = __ldcg(Lr + lane + 32);
                float a = l0.x * ha.x + l0.y * ha.y + l0.z * ha.z + l0.w * ha.w
                        + l1.x * hb.x + l1.y * hb.y + l1.z * hb.z + l1.w * hb.w;
                #pragma unroll
                for (int o = 16; o; o >>= 1) a += __shfl_xor_sync(0xffffffffu, a, o);
                if (lane == 0) S.ls[wb][j] = CLIPV * tanhf(a * INV_SQRT_D);
            }
        }
        __syncthreads();

        // ---- argmax + log-softmax at selected (warp bb) -------------------
        if (warp < NB) {
            const int bb = warp;
            float m = NEGV; int mj = 0;
            for (int j = lane; j < cnt; j += 32) {
                float v = S.ls[bb][j];
                if (v > m) { m = v; mj = j; }
            }
            #pragma unroll
            for (int o = 16; o; o >>= 1) {
                float vm = __shfl_xor_sync(0xffffffffu, m, o);
                int   vj = __shfl_xor_sync(0xffffffffu, mj, o);
                if (vm > m || (vm == m && vj < mj)) { m = vm; mj = vj; }
            }
            float s = 0.f;
            for (int j = lane; j < cnt; j += 32) s += expf(S.ls[bb][j] - m);
            #pragma unroll
            for (int o = 16; o; o >>= 1) s += __shfl_xor_sync(0xffffffffu, s, o);
            if (lane == 0) {
                int node = S.list[bb][mj];
                S.sel[bb] = node;
                ll += S.ls[bb][mj] - (m + logf(s));
                float cx = coords[((size_t)(b0 + bb) * Nn + node) * 2 + 0];
                float cy = coords[((size_t)(b0 + bb) * Nn + node) * 2 + 1];
                if (t == 0) { fx = cx; fy = cy; }
                else {
                    float dx = cx - px, dy = cy - py;
                    cost += sqrtf(dx * dx + dy * dy);
                }
                px = cx; py = cy;
                S.list[bb][mj] = S.list[bb][cnt - 1];
            }
        }
        if (tid == 0) S.cnt = cnt - 1;
        __syncthreads();

        if (t == 0) {   // fctx[bb] = E[b,first] @ Ws_top
            #pragma unroll
            for (int bb = 0; bb < NB; bb++)
                S.er[bb][tid] =
                    E[((size_t)(b0 + bb) * Nn + S.sel[bb]) * Dd + tid];
            __syncthreads();
            float f[NB] = {0.f, 0.f};
            #pragma unroll 8
            for (int k = 0; k < Dd; k++) {
                float wv = Ws[k * Dd + tid];
                #pragma unroll
                for (int bb = 0; bb < NB; bb++) f[bb] += S.er[bb][k] * wv;
            }
            #pragma unroll
            for (int bb = 0; bb < NB; bb++) fctx[bb] = f[bb];
            __syncthreads();
        }

        if (t < Nn - 1) {   // next raw query: mv + fctx + P[sel]
            float q0v = fctx[0] + mv0 +
                __ldcg(&g_P[((size_t)(b0 + 0) * Nn + S.sel[0]) * Dd + tid]);
            float q1v = fctx[1] + mv1 +
                __ldcg(&g_P[((size_t)(b0 + 1) * Nn + S.sel[1]) * Dd + tid]);
            S.q[0][tid] = q0v;
            S.q[1][tid] = q1v;
            k4_finalize_q(S, tid, mlp, W1, b1, W2, b2);
        }
    }

    if (warp < NB && lane == 0) {
        float dx = px - fx, dy = py - fy;
        cost += sqrtf(dx * dx + dy * dy);
        out[b0 + warp]      = cost;
        out[Bq + b0 + warp] = ll;
    }
}

// ---------------- launcher ---------------------------------------------------
extern "C" void kernel_launch(void* const* d_in, const int* in_sizes, int n_in,
                              void* d_out, int out_size)
{
    const float* coords = (const float*)d_in[0];
    const float* E      = (const float*)d_in[1];
    const float* Wk     = (const float*)d_in[2];
    const float* Wv     = (const float*)d_in[3];
    const float* Wlk    = (const float*)d_in[4];
    const float* Wo     = (const float*)d_in[5];
    const float* Wc     = (const float*)d_in[6];
    const float* Ws     = (const float*)d_in[7];
    const float* Wph    = (const float*)d_in[8];
    const float* W1     = (const float*)d_in[9];
    const float* b1     = (const float*)d_in[10];
    const float* W2     = (const float*)d_in[11];
    const float* b2     = (const float*)d_in[12];
    float* out = (float*)d_out;

    const int k4_smem = (int)sizeof(K4Smem);
    cudaFuncSetAttribute(k4_decode, cudaFuncAttributeMaxDynamicSharedMemorySize,
                         k4_smem);
    cudaFuncSetAttribute(k3t_mma, cudaFuncAttributeMaxDynamicSharedMemorySize,
                         K3T_SMEM);

    k0_prep<<<2, 256>>>(Wo, W2, b2);
    k1_weights<<<513, 256>>>(Wo, Wc, Wlk, Ws, Wph);
    k_splitE<<<8192, 256>>>(E);
    {
        dim3 gw(4, 256);
        k_splitW<<<gw, 256>>>(Wk, Wv, Ws);
    }
    k2_q0<<<Bq, 256>>>(E, Wc);
    {
        dim3 g3(ROWS_TOTAL / 128, 2, 4);
        k3t_mma<<<g3, 256, K3T_SMEM>>>();
    }
    k4_decode<<<Bq / NB, 256, k4_smem>>>(E, coords, Ws, W1, b1, W2, b2, out);
}

// round 13
// speedup vs baseline: 1.3820x; 1.3820x over previous
#include <cuda_runtime.h>
#include <cuda_fp16.h>
#include <cstdint>

// Problem constants
#define Bq   1024
#define Nn   128
#define Dd   256
#define Hh   8
#define NB   2
#define NEGV (-1e9f)
#define CLIPV 10.0f
#define INV_SQRT_DH 0.17677669529663687f  // 1/sqrt(32)
#define INV_SQRT_D  0.0625f               // 1/sqrt(256)

#define ROWS_TOTAL (Bq * Nn)              // 131072
#define WSCALE     16.0f                  // W pre-scale (exact pow2)
#define WUNSCALE   0.0625f                // 1/16

// ---------------- scratch (device globals; no cudaMalloc allowed) ----------
__device__ float g_K   [Bq * Nn * Dd];   // [b][n][d]  (E@Wk)
__device__ float g_V   [Bq * Nn * Dd];   // [b][n][d]  (E@Wv)
__device__ float g_LK2 [Bq * Nn * Dd];   // [b][n][d]  (E@(Wlk@Wo^T))
__device__ float g_P   [Bq * Nn * Dd];   // [b][n][d]  (E@Ws_bot)
__device__ float g_q0  [Bq * Dd];        // step-0 query (pre-MLP)
__device__ float g_Woc [Dd * Dd];        // Wo@Wc
__device__ float g_Wlk2[Dd * Dd];        // Wlk@Wo^T
__device__ float g_pc  [Dd];             // W_placeholder @ Ws
__device__ int   g_mlp;                  // 1 if (W2,b2) nonzero -> general path

// fp16 2-way splits (x ~= h0+h1 to ~2^-22)
__device__ __half g_Es[2][ROWS_TOTAL * Dd];     // E splits
__device__ __half g_Wt[2][4][Dd * Dd];          // (16*W)^T splits [s][w][n][k]

// ================= helpers ==================================================
__device__ __forceinline__ uint32_t smem_u32(const void* p) {
    uint32_t a;
    asm("{ .reg .u64 t; cvta.to.shared.u64 t, %1; cvt.u32.u64 %0, t; }"
        : "=r"(a) : "l"(p));
    return a;
}
__device__ __forceinline__ void ldsm_x4(uint32_t* r, uint32_t addr) {
    asm volatile("ldmatrix.sync.aligned.m8n8.x4.shared.b16 {%0,%1,%2,%3}, [%4];"
        : "=r"(r[0]), "=r"(r[1]), "=r"(r[2]), "=r"(r[3]) : "r"(addr));
}
__device__ __forceinline__ void mma_fp16(float* c, const uint32_t* a, const uint32_t* b) {
    asm volatile("mma.sync.aligned.m16n8k16.row.col.f32.f16.f16.f32 "
        "{%0,%1,%2,%3}, {%4,%5,%6,%7}, {%8,%9}, {%0,%1,%2,%3};"
        : "+f"(c[0]), "+f"(c[1]), "+f"(c[2]), "+f"(c[3])
        : "r"(a[0]), "r"(a[1]), "r"(a[2]), "r"(a[3]), "r"(b[0]), "r"(b[1]));
}
__device__ __forceinline__ void cp_async16(uint32_t dst, const void* src) {
    asm volatile("cp.async.cg.shared.global [%0], [%1], 16;"
                 :: "r"(dst), "l"(src) : "memory");
}
#define CP_COMMIT() asm volatile("cp.async.commit_group;" ::: "memory")
#define CP_WAIT0()  asm volatile("cp.async.wait_group 0;" ::: "memory")

// buffer offsets (macros: device-safe)
#define K3_ABUF(p) ((p) * 16384)
#define K3_BBUF(p) (32768 + (p) * 16384)
#define K3T_SMEM   65536

#define DOT4(u, v) ((u).x * (v).x + (u).y * (v).y + (u).z * (v).z + (u).w * (v).w)

// ---------------- k1: Woc = Wo@Wc ; Wlk2 = Wlk@Wo^T ; pc ; mlp-detect ------
// Wlk2[m][d] = sum_j Wlk[m][j] * Wo[d][j]  (no explicit transpose needed)
__global__ void k1_weights(const float* __restrict__ Wo,
                           const float* __restrict__ Wc,
                           const float* __restrict__ Wlk,
                           const float* __restrict__ Ws,
                           const float* __restrict__ Wph,
                           const float* __restrict__ W2,
                           const float* __restrict__ b2)
{
    int bid = blockIdx.x;
    int d = threadIdx.x;
    if (bid < 256) {               // Woc row bid
        float acc = 0.f;
        #pragma unroll 8
        for (int j = 0; j < Dd; j++) acc += Wo[bid * Dd + j] * Wc[j * Dd + d];
        g_Woc[bid * Dd + d] = acc;
    } else if (bid < 512) {        // Wlk2 row m
        int m = bid - 256;
        __shared__ float lr[Dd];
        lr[d] = Wlk[m * Dd + d];
        __syncthreads();
        const float* Wod = Wo + (size_t)d * Dd;
        float a0 = 0.f, a1 = 0.f;
        #pragma unroll 8
        for (int j = 0; j < Dd; j += 2) {
            a0 += lr[j]     * Wod[j];
            a1 += lr[j + 1] * Wod[j + 1];
        }
        g_Wlk2[m * Dd + d] = a0 + a1;
    } else if (bid == 512) {       // pc
        float acc = 0.f;
        #pragma unroll 8
        for (int k = 0; k < 2 * Dd; k++) acc += Wph[k] * Ws[k * Dd + d];
        g_pc[d] = acc;
    } else {                       // mlp-nonzero detect
        __shared__ int any;
        if (d == 0) any = 0;
        __syncthreads();
        int loc = 0;
        for (int i = d; i < Dd * Dd; i += blockDim.x) loc |= (W2[i] != 0.0f);
        loc |= (b2[d] != 0.0f);
        if (loc) atomicOr(&any, 1);
        __syncthreads();
        if (d == 0) g_mlp = any;
    }
}

// ---------------- k2: q0 = mean_n(E) @ Wc + pc ------------------------------
__global__ void k2_q0(const float* __restrict__ E, const float* __restrict__ Wc)
{
    int b = blockIdx.x, d = threadIdx.x;
    __shared__ float g[Dd];
    float s = 0.f;
    const float* Eb = E + (size_t)b * Nn * Dd + d;
    #pragma unroll 8
    for (int n = 0; n < Nn; n++) s += Eb[n * Dd];
    g[d] = s * (1.0f / Nn);
    __syncthreads();
    float acc = g_pc[d];
    #pragma unroll 8
    for (int k = 0; k < Dd; k++) acc += g[k] * Wc[k * Dd + d];
    g_q0[b * Dd + d] = acc;
}

// ---------------- split kernels: fp32 -> 2x fp16 (to ~2^-22) ----------------
__global__ void k_splitE(const float* __restrict__ E)
{
    const size_t total = (size_t)ROWS_TOTAL * Dd;
    const size_t stride = (size_t)gridDim.x * blockDim.x;
    for (size_t i = (size_t)blockIdx.x * blockDim.x + threadIdx.x; i < total; i += stride) {
        float x = E[i];
        __half h0 = __float2half_rn(x);
        float r = x - __half2float(h0);
        __half h1 = __float2half_rn(r);
        g_Es[0][i] = h0; g_Es[1][i] = h1;
    }
}

// transposed weight splits of 16*W: g_Wt[s][w][n*256+k] = split_s(16 * W_w[k][n])
__global__ void k_splitW(const float* __restrict__ Wk,
                         const float* __restrict__ Wv,
                         const float* __restrict__ Ws)
{
    const int w = blockIdx.x, n = blockIdx.y, k = threadIdx.x;
    const float* src;
    if      (w == 0) src = Wk;
    else if (w == 1) src = Wv;
    else if (w == 2) src = g_Wlk2;
    else             src = Ws + Dd * Dd;
    float x = src[k * Dd + n] * WSCALE;
    __half h0 = __float2half_rn(x);
    float r = x - __half2float(h0);
    __half h1 = __float2half_rn(r);
    g_Wt[0][w][n * Dd + k] = h0;
    g_Wt[1][w][n * Dd + k] = h1;
}

// ---------------- k3t: mma.sync fp16-2split GEMM, cp.async pipelined --------
__global__ void __launch_bounds__(256, 2) k3t_mma()
{
    extern __shared__ char smem[];
    const uint32_t sbase = smem_u32(smem);
    const int tid = threadIdx.x;
    const int warp = tid >> 5, lane = tid & 31;
    const int rowbase = blockIdx.x * 128;
    const int nbase   = blockIdx.y * 128;
    const int w       = blockIdx.z;

    float* out;
    if      (w == 0) out = g_K;
    else if (w == 1) out = g_V;
    else if (w == 2) out = g_LK2;
    else             out = g_P;

    const int wm = warp & 3;      // 4 m-blocks of 32 rows
    const int wn = warp >> 2;     // 2 n-blocks of 64 cols

    float acc[2][8][4] = {};      // [mblk16][nblk8][frag]

    uint32_t st_dst[8];
    const __half* st_src[8];
    #pragma unroll
    for (int it = 0; it < 8; it++) {
        int i = tid + it * 256;
        int reg = i >> 10, s = (i >> 9) & 1, row = (i >> 2) & 127, q = i & 3;
        uint32_t off = (uint32_t)(s * 8192 + row * 64 + ((q * 16) ^ ((row & 6) << 3)));
        if (reg == 0) {
            st_dst[it] = off;
            st_src[it] = &g_Es[s][(size_t)(rowbase + row) * Dd + q * 8];
        } else {
            st_dst[it] = 32768u + off;
            st_src[it] = &g_Wt[s][w][(size_t)(nbase + row) * Dd + q * 8];
        }
    }

    uint32_t a_off[2], a_mask[2];
    #pragma unroll
    for (int mb = 0; mb < 2; mb++) {
        int row = wm * 32 + mb * 16 + (lane & 15);
        a_off[mb]  = (uint32_t)(row * 64);
        a_mask[mb] = (uint32_t)(((row & 6) << 3) ^ ((lane >> 4) * 16));
    }
    uint32_t b_off[4], b_mask[4];
    #pragma unroll
    for (int p = 0; p < 4; p++) {
        int pr = lane >> 3;
        int nrow = wn * 64 + p * 16 + ((pr >> 1) << 3) + (lane & 7);
        b_off[p]  = (uint32_t)(nrow * 64);
        b_mask[p] = (uint32_t)(((nrow & 6) << 3) ^ ((pr & 1) * 16));
    }

    {
        const uint32_t abase = sbase + K3_ABUF(0);
        #pragma unroll
        for (int it = 0; it < 8; it++)
            cp_async16(abase + st_dst[it], st_src[it]);
        CP_COMMIT();
    }

    for (int c = 0; c < 8; c++) {
        CP_WAIT0();
        __syncthreads();

        if (c + 1 < 8) {
            const uint32_t abase = sbase + K3_ABUF((c + 1) & 1);
            const int kadv = (c + 1) * 32;
            #pragma unroll
            for (int it = 0; it < 8; it++)
                cp_async16(abase + st_dst[it], st_src[it] + kadv);
            CP_COMMIT();
        }

        const uint32_t Ab = sbase + K3_ABUF(c & 1);
        const uint32_t Bb = sbase + K3_BBUF(c & 1);

        #pragma unroll
        for (int ks = 0; ks < 2; ks++) {
            const uint32_t kx = (uint32_t)(ks * 32);
            uint32_t af[2][2][4];
            #pragma unroll
            for (int s = 0; s < 2; s++)
                #pragma unroll
                for (int mb = 0; mb < 2; mb++)
                    ldsm_x4(af[s][mb], Ab + s * 8192 + a_off[mb] + (kx ^ a_mask[mb]));
            #pragma unroll
            for (int p = 0; p < 4; p++) {
                uint32_t b0[4];
                ldsm_x4(b0, Bb + b_off[p] + (kx ^ b_mask[p]));
                #pragma unroll
                for (int sa = 0; sa < 2; sa++) {
                    mma_fp16(acc[0][2 * p],     af[sa][0], b0 + 0);
                    mma_fp16(acc[0][2 * p + 1], af[sa][0], b0 + 2);
                    mma_fp16(acc[1][2 * p],     af[sa][1], b0 + 0);
                    mma_fp16(acc[1][2 * p + 1], af[sa][1], b0 + 2);
                }
                uint32_t b1[4];
                ldsm_x4(b1, Bb + 8192 + b_off[p] + (kx ^ b_mask[p]));
                mma_fp16(acc[0][2 * p],     af[0][0], b1 + 0);
                mma_fp16(acc[0][2 * p + 1], af[0][0], b1 + 2);
                mma_fp16(acc[1][2 * p],     af[0][1], b1 + 0);
                mma_fp16(acc[1][2 * p + 1], af[0][1], b1 + 2);
            }
        }
        __syncthreads();
    }

    const int r0 = rowbase + wm * 32 + (lane >> 2);
    const int c0 = nbase + wn * 64 + (lane & 3) * 2;
    #pragma unroll
    for (int mb = 0; mb < 2; mb++)
        #pragma unroll
        for (int nb = 0; nb < 8; nb++) {
            float2 lo = make_float2(acc[mb][nb][0] * WUNSCALE, acc[mb][nb][1] * WUNSCALE);
            float2 hi = make_float2(acc[mb][nb][2] * WUNSCALE, acc[mb][nb][3] * WUNSCALE);
            *(float2*)(out + (size_t)(r0 + mb * 16)     * Dd + c0 + nb * 8) = lo;
            *(float2*)(out + (size_t)(r0 + mb * 16 + 8) * Dd + c0 + nb * 8) = hi;
        }
}

// ---------------- k4: persistent decode, NB=2 batches per block -------------
struct K4Smem {
    float q[NB][Dd];
    float heads[NB][Dd];
    float cc[NB][Nn][9];
    float pp[NB][Hh][Nn + 4];
    float ls[NB][Nn];
    int   list[NB][Nn];
    float er[NB][Dd];
    float sum[NB][Hh];
    int   sel[NB];
    int   cnt;
};

__device__ __forceinline__ void k4_finalize_q(K4Smem& S, int tid, int mlp,
                                              const float* __restrict__ W1,
                                              const float* __restrict__ b1,
                                              const float* __restrict__ W2,
                                              const float* __restrict__ b2)
{
    if (mlp) {
        __syncthreads();
        float m1[NB];
        #pragma unroll
        for (int bb = 0; bb < NB; bb++) m1[bb] = b1[tid];
        #pragma unroll 8
        for (int k = 0; k < Dd; k++) {
            float wv = W1[k * Dd + tid];
            #pragma unroll
            for (int bb = 0; bb < NB; bb++) m1[bb] += S.q[bb][k] * wv;
        }
        #pragma unroll
        for (int bb = 0; bb < NB; bb++) S.er[bb][tid] = fmaxf(m1[bb], 0.0f);
        __syncthreads();
        float m2[NB];
        #pragma unroll
        for (int bb = 0; bb < NB; bb++) m2[bb] = b2[tid];
        #pragma unroll 8
        for (int k = 0; k < Dd; k++) {
            float wv = W2[k * Dd + tid];
            #pragma unroll
            for (int bb = 0; bb < NB; bb++) m2[bb] += S.er[bb][k] * wv;
        }
        __syncthreads();
        #pragma unroll
        for (int bb = 0; bb < NB; bb++)
            S.q[bb][tid] = (S.q[bb][tid] + m2[bb]) * INV_SQRT_DH;
    } else {
        #pragma unroll
        for (int bb = 0; bb < NB; bb++) S.q[bb][tid] *= INV_SQRT_DH;
    }
    __syncthreads();
}

__global__ void __launch_bounds__(256, 4) k4_decode(const float* __restrict__ E,
                                                    const float* __restrict__ coords,
                                                    const float* __restrict__ Ws,
                                                    const float* __restrict__ W1,
                                                    const float* __restrict__ b1,
                                                    const float* __restrict__ W2,
                                                    const float* __restrict__ b2,
                                                    float* __restrict__ out)
{
    extern __shared__ char smem_raw[];
    K4Smem& S = *(K4Smem*)smem_raw;

    const int b0 = blockIdx.x * NB;
    const int tid = threadIdx.x;
    const int warp = tid >> 5, lane = tid & 31;
    const int wb  = warp >> 2;
    const int wj0 = warp & 3;
    const int mlp = g_mlp;

    if (tid < Nn) {
        #pragma unroll
        for (int bb = 0; bb < NB; bb++) S.list[bb][tid] = tid;
    }
    if (tid == 0) S.cnt = Nn;
    #pragma unroll
    for (int bb = 0; bb < NB; bb++)
        S.q[bb][tid] = g_q0[(b0 + bb) * Dd + tid];
    k4_finalize_q(S, tid, mlp, W1, b1, W2, b2);

    const float* Kbase  = g_K   + (size_t)b0 * Nn * Dd;
    const float* Vbase  = g_V   + (size_t)b0 * Nn * Dd;
    const float* LKbase = g_LK2 + (size_t)b0 * Nn * Dd;

    float ll = 0.f, cost = 0.f;
    float fx = 0.f, fy = 0.f, px = 0.f, py = 0.f;
    float fctx[NB] = {0.f, 0.f};

    for (int t = 0; t < Nn; t++) {
        const int cnt = S.cnt;

        {   // ---- compat: two rows per iteration (4 LDG.128 in flight) -----
            const float4* q4 = (const float4*)S.q[wb];
            float4 qa = q4[lane], qb = q4[lane + 32];
            const float* Kb = Kbase + (size_t)wb * Nn * Dd;
            const int* lst = S.list[wb];
            for (int j = wj0; j < cnt; j += 8) {
                const int j2 = j + 4;
                const bool h2 = (j2 < cnt);
                const float4* Kr0 = (const float4*)(Kb + (size_t)lst[j] * Dd);
                const float4* Kr1 = (const float4*)(Kb + (size_t)lst[h2 ? j2 : j] * Dd);
                float4 x0 = __ldcg(Kr0 + lane);
                float4 x1 = __ldcg(Kr0 + lane + 32);
                float4 y0 = __ldcg(Kr1 + lane);
                float4 y1 = __ldcg(Kr1 + lane + 32);
                float alo = DOT4(x0, qa), ahi = DOT4(x1, qb);
                float blo = DOT4(y0, qa), bhi = DOT4(y1, qb);
                #pragma unroll
                for (int o = 1; o < 8; o <<= 1) {
                    alo += __shfl_xor_sync(0xffffffffu, alo, o);
                    ahi += __shfl_xor_sync(0xffffffffu, ahi, o);
                    blo += __shfl_xor_sync(0xffffffffu, blo, o);
                    bhi += __shfl_xor_sync(0xffffffffu, bhi, o);
                }
                if ((lane & 7) == 0) {
                    int hg = lane >> 3;
                    S.cc[wb][j][hg]     = alo;
                    S.cc[wb][j][4 + hg] = ahi;
                    if (h2) {
                        S.cc[wb][j2][hg]     = blo;
                        S.cc[wb][j2][4 + hg] = bhi;
                    }
                }
            }
        }
        __syncthreads();

        {   // ---- softmax ----
            const int h = warp;
            #pragma unroll
            for (int bb = 0; bb < NB; bb++) {
                float m = NEGV;
                for (int j = lane; j < cnt; j += 32) m = fmaxf(m, S.cc[bb][j][h]);
                #pragma unroll
                for (int o = 16; o; o >>= 1)
                    m = fmaxf(m, __shfl_xor_sync(0xffffffffu, m, o));
                float s = 0.f;
                for (int j = lane; j < cnt; j += 32) {
                    float e = expf(S.cc[bb][j][h] - m);
                    S.pp[bb][h][j] = e;
                    s += e;
                }
                #pragma unroll
                for (int o = 16; o; o >>= 1) s += __shfl_xor_sync(0xffffffffu, s, o);
                if (lane == 0) S.sum[bb][h] = s;
            }
        }
        __syncthreads();

        {   // ---- heads: 2 accumulators x NB, unroll 2 (8 loads in flight) --
            const int d = tid, h = tid >> 5;
            float a0[NB] = {0.f, 0.f}, a1[NB] = {0.f, 0.f};
            const float* Vd = Vbase + d;
            int j = 0;
            #pragma unroll 2
            for (; j + 2 <= cnt; j += 2) {
                #pragma unroll
                for (int bb = 0; bb < NB; bb++) {
                    a0[bb] += S.pp[bb][h][j] *
                              __ldcg(Vd + ((size_t)bb * Nn + S.list[bb][j]) * Dd);
                    a1[bb] += S.pp[bb][h][j + 1] *
                              __ldcg(Vd + ((size_t)bb * Nn + S.list[bb][j + 1]) * Dd);
                }
            }
            if (j < cnt) {
                #pragma unroll
                for (int bb = 0; bb < NB; bb++)
                    a0[bb] += S.pp[bb][h][j] *
                              __ldcg(Vd + ((size_t)bb * Nn + S.list[bb][j]) * Dd);
            }
            #pragma unroll
            for (int bb = 0; bb < NB; bb++)
                S.heads[bb][d] = (a0[bb] + a1[bb]) / S.sum[bb][h];
        }
        __syncthreads();

        // ---- Woc matvec (result registers; overlaps logits phase) ---------
        float mv0 = 0.f, mv1 = 0.f;
        if (t < Nn - 1) {
            float a0 = 0.f, a1 = 0.f, b0a = 0.f, b1a = 0.f;
            const float* Wp = g_Woc + tid;
            #pragma unroll 8
            for (int k = 0; k < Dd; k += 2) {
                float wv0 = Wp[(size_t)k * Dd];
                float wv1 = Wp[(size_t)(k + 1) * Dd];
                a0  += S.heads[0][k]     * wv0;
                b0a += S.heads[1][k]     * wv0;
                a1  += S.heads[0][k + 1] * wv1;
                b1a += S.heads[1][k + 1] * wv1;
            }
            mv0 = a0 + a1;
            mv1 = b0a + b1a;
        }

        {   // ---- logits: two rows per iteration ---------------------------
            const float4* h4 = (const float4*)S.heads[wb];
            float4 ha = h4[lane], hb = h4[lane + 32];
            const float* Lb = LKbase + (size_t)wb * Nn * Dd;
            const int* lst = S.list[wb];
            for (int j = wj0; j < cnt; j += 8) {
                const int j2 = j + 4;
                const bool h2 = (j2 < cnt);
                const float4* Lr0 = (const float4*)(Lb + (size_t)lst[j] * Dd);
                const float4* Lr1 = (const float4*)(Lb + (size_t)lst[h2 ? j2 : j] * Dd);
                float4 x0 = __ldcg(Lr0 + lane);
                float4 x1 = __ldcg(Lr0 + lane + 32);
                float4 y0 = __ldcg(Lr1 + lane);
                float4 y1 = __ldcg(Lr1 + lane + 32);
                float a = DOT4(x0, ha) + DOT4(x1, hb);
                float b = DOT4(y0, ha) + DOT4(y1, hb);
                #pragma unroll
                for (int o = 16; o; o >>= 1) {
                    a += __shfl_xor_sync(0xffffffffu, a, o);
                    b += __shfl_xor_sync(0xffffffffu, b, o);
                }
                if (lane == 0) {
                    S.ls[wb][j] = CLIPV * tanhf(a * INV_SQRT_D);
                    if (h2) S.ls[wb][j2] = CLIPV * tanhf(b * INV_SQRT_D);
                }
            }
        }
        __syncthreads();

        // ---- argmax + log-softmax at selected (warp bb) -------------------
        if (warp < NB) {
            const int bb = warp;
            float m = NEGV; int mj = 0;
            for (int j = lane; j < cnt; j += 32) {
                float v = S.ls[bb][j];
                if (v > m) { m = v; mj = j; }
            }
            #pragma unroll
            for (int o = 16; o; o >>= 1) {
                float vm = __shfl_xor_sync(0xffffffffu, m, o);
                int   vj = __shfl_xor_sync(0xffffffffu, mj, o);
                if (vm > m || (vm == m && vj < mj)) { m = vm; mj = vj; }
            }
            float s = 0.f;
            for (int j = lane; j < cnt; j += 32) s += expf(S.ls[bb][j] - m);
            #pragma unroll
            for (int o = 16; o; o >>= 1) s += __shfl_xor_sync(0xffffffffu, s, o);
            if (lane == 0) {
                int node = S.list[bb][mj];
                S.sel[bb] = node;
                ll += S.ls[bb][mj] - (m + logf(s));
                float cx = coords[((size_t)(b0 + bb) * Nn + node) * 2 + 0];
                float cy = coords[((size_t)(b0 + bb) * Nn + node) * 2 + 1];
                if (t == 0) { fx = cx; fy = cy; }
                else {
                    float dx = cx - px, dy = cy - py;
                    cost += sqrtf(dx * dx + dy * dy);
                }
                px = cx; py = cy;
                S.list[bb][mj] = S.list[bb][cnt - 1];
            }
        }
        if (tid == 0) S.cnt = cnt - 1;
        __syncthreads();

        if (t == 0) {   // fctx[bb] = E[b,first] @ Ws_top
            #pragma unroll
            for (int bb = 0; bb < NB; bb++)
                S.er[bb][tid] =
                    E[((size_t)(b0 + bb) * Nn + S.sel[bb]) * Dd + tid];
            __syncthreads();
            float f[NB] = {0.f, 0.f};
            #pragma unroll 8
            for (int k = 0; k < Dd; k++) {
                float wv = Ws[k * Dd + tid];
                #pragma unroll
                for (int bb = 0; bb < NB; bb++) f[bb] += S.er[bb][k] * wv;
            }
            #pragma unroll
            for (int bb = 0; bb < NB; bb++) fctx[bb] = f[bb];
            __syncthreads();
        }

        if (t < Nn - 1) {   // next raw query: mv + fctx + P[sel]
            float q0v = fctx[0] + mv0 +
                __ldcg(&g_P[((size_t)(b0 + 0) * Nn + S.sel[0]) * Dd + tid]);
            float q1v = fctx[1] + mv1 +
                __ldcg(&g_P[((size_t)(b0 + 1) * Nn + S.sel[1]) * Dd + tid]);
            S.q[0][tid] = q0v;
            S.q[1][tid] = q1v;
            k4_finalize_q(S, tid, mlp, W1, b1, W2, b2);
        }
    }

    if (warp < NB && lane == 0) {
        float dx = px - fx, dy = py - fy;
        cost += sqrtf(dx * dx + dy * dy);
        out[b0 + warp]      = cost;
        out[Bq + b0 + warp] = ll;
    }
}

// ---------------- launcher ---------------------------------------------------
extern "C" void kernel_launch(void* const* d_in, const int* in_sizes, int n_in,
                              void* d_out, int out_size)
{
    const float* coords = (const float*)d_in[0];
    const float* E      = (const float*)d_in[1];
    const float* Wk     = (const float*)d_in[2];
    const float* Wv     = (const float*)d_in[3];
    const float* Wlk    = (const float*)d_in[4];
    const float* Wo     = (const float*)d_in[5];
    const float* Wc     = (const float*)d_in[6];
    const float* Ws     = (const float*)d_in[7];
    const float* Wph    = (const float*)d_in[8];
    const float* W1     = (const float*)d_in[9];
    const float* b1     = (const float*)d_in[10];
    const float* W2     = (const float*)d_in[11];
    const float* b2     = (const float*)d_in[12];
    float* out = (float*)d_out;

    const int k4_smem = (int)sizeof(K4Smem);
    cudaFuncSetAttribute(k4_decode, cudaFuncAttributeMaxDynamicSharedMemorySize,
                         k4_smem);
    cudaFuncSetAttribute(k3t_mma, cudaFuncAttributeMaxDynamicSharedMemorySize,
                         K3T_SMEM);

    // order chosen so the ncu capture slot (our 4th launch) lands on k3t
    k1_weights<<<514, 256>>>(Wo, Wc, Wlk, Ws, Wph, W2, b2);
    k_splitE<<<8192, 256>>>(E);
    {
        dim3 gw(4, 256);
        k_splitW<<<gw, 256>>>(Wk, Wv, Ws);
    }
    {
        dim3 g3(ROWS_TOTAL / 128, 2, 4);
        k3t_mma<<<g3, 256, K3T_SMEM>>>();
    }
    k2_q0<<<Bq, 256>>>(E, Wc);
    k4_decode<<<Bq / NB, 256, k4_smem>>>(E, coords, Ws, W1, b1, W2, b2, out);
}

// round 14
// speedup vs baseline: 1.6492x; 1.1933x over previous
#include <cuda_runtime.h>
#include <cuda_fp16.h>
#include <cstdint>

// Problem constants
#define Bq   1024
#define Nn   128
#define Dd   256
#define Hh   8
#define NB   2
#define NEGV (-1e9f)
#define CLIPV 10.0f
#define INV_SQRT_DH 0.17677669529663687f  // 1/sqrt(32)
#define INV_SQRT_D  0.0625f               // 1/sqrt(256)

#define ROWS_TOTAL (Bq * Nn)              // 131072
#define WSCALE     16.0f                  // W pre-scale (exact pow2)
#define WUNSCALE   0.0625f                // 1/16

// ---------------- scratch (device globals; no cudaMalloc allowed) ----------
__device__ float g_K   [Bq * Nn * Dd];   // [b][n][d]  (E@Wk)
__device__ float g_V   [Bq * Nn * Dd];   // [b][n][d]  (E@Wv)
__device__ float g_LK2 [Bq * Nn * Dd];   // [b][n][d]  (E@(Wlk@Wo^T))
__device__ float g_P   [Bq * Nn * Dd];   // [b][n][d]  (E@Ws_bot)
__device__ float g_q0  [Bq * Dd];        // step-0 query (pre-MLP)
__device__ float g_Woc [Dd * Dd];        // Wo@Wc
__device__ float g_Wlk2[Dd * Dd];        // Wlk@Wo^T
__device__ float g_pc  [Dd];             // W_placeholder @ Ws
__device__ int   g_mlp;                  // 1 if (W2,b2) nonzero -> general path

// fp16 2-way splits (x ~= h0+h1 to ~2^-22)
__device__ __half g_Es[2][ROWS_TOTAL * Dd];     // E splits
__device__ __half g_Wt[2][4][Dd * Dd];          // (16*W)^T splits [s][w][n][k]

// ================= helpers ==================================================
__device__ __forceinline__ uint32_t smem_u32(const void* p) {
    uint32_t a;
    asm("{ .reg .u64 t; cvta.to.shared.u64 t, %1; cvt.u32.u64 %0, t; }"
        : "=r"(a) : "l"(p));
    return a;
}
__device__ __forceinline__ void ldsm_x4(uint32_t* r, uint32_t addr) {
    asm volatile("ldmatrix.sync.aligned.m8n8.x4.shared.b16 {%0,%1,%2,%3}, [%4];"
        : "=r"(r[0]), "=r"(r[1]), "=r"(r[2]), "=r"(r[3]) : "r"(addr));
}
__device__ __forceinline__ void mma_fp16(float* c, const uint32_t* a, const uint32_t* b) {
    asm volatile("mma.sync.aligned.m16n8k16.row.col.f32.f16.f16.f32 "
        "{%0,%1,%2,%3}, {%4,%5,%6,%7}, {%8,%9}, {%0,%1,%2,%3};"
        : "+f"(c[0]), "+f"(c[1]), "+f"(c[2]), "+f"(c[3])
        : "r"(a[0]), "r"(a[1]), "r"(a[2]), "r"(a[3]), "r"(b[0]), "r"(b[1]));
}
__device__ __forceinline__ void cp_async16(uint32_t dst, const void* src) {
    asm volatile("cp.async.cg.shared.global [%0], [%1], 16;"
                 :: "r"(dst), "l"(src) : "memory");
}
#define CP_COMMIT() asm volatile("cp.async.commit_group;" ::: "memory")
#define CP_WAIT0()  asm volatile("cp.async.wait_group 0;" ::: "memory")

// buffer offsets (macros: device-safe)
#define K3_ABUF(p) ((p) * 16384)
#define K3_BBUF(p) (32768 + (p) * 16384)
#define K3T_SMEM   65536

#define DOT4(u, v) ((u).x * (v).x + (u).y * (v).y + (u).z * (v).z + (u).w * (v).w)

// ---------------- k1: Woc = Wo@Wc ; Wlk2 = Wlk@Wo^T ; pc ; mlp-detect ------
__global__ void k1_weights(const float* __restrict__ Wo,
                           const float* __restrict__ Wc,
                           const float* __restrict__ Wlk,
                           const float* __restrict__ Ws,
                           const float* __restrict__ Wph,
                           const float* __restrict__ W2,
                           const float* __restrict__ b2)
{
    int bid = blockIdx.x;
    int d = threadIdx.x;
    if (bid < 256) {               // Woc row bid
        float acc = 0.f;
        #pragma unroll 8
        for (int j = 0; j < Dd; j++) acc += Wo[bid * Dd + j] * Wc[j * Dd + d];
        g_Woc[bid * Dd + d] = acc;
    } else if (bid < 512) {        // Wlk2 row m
        int m = bid - 256;
        __shared__ float lr[Dd];
        lr[d] = Wlk[m * Dd + d];
        __syncthreads();
        const float* Wod = Wo + (size_t)d * Dd;
        float a0 = 0.f, a1 = 0.f;
        #pragma unroll 8
        for (int j = 0; j < Dd; j += 2) {
            a0 += lr[j]     * Wod[j];
            a1 += lr[j + 1] * Wod[j + 1];
        }
        g_Wlk2[m * Dd + d] = a0 + a1;
    } else if (bid == 512) {       // pc
        float acc = 0.f;
        #pragma unroll 8
        for (int k = 0; k < 2 * Dd; k++) acc += Wph[k] * Ws[k * Dd + d];
        g_pc[d] = acc;
    } else {                       // mlp-nonzero detect
        __shared__ int any;
        if (d == 0) any = 0;
        __syncthreads();
        int loc = 0;
        for (int i = d; i < Dd * Dd; i += blockDim.x) loc |= (W2[i] != 0.0f);
        loc |= (b2[d] != 0.0f);
        if (loc) atomicOr(&any, 1);
        __syncthreads();
        if (d == 0) g_mlp = any;
    }
}

// ---------------- k2: q0 = mean_n(E) @ Wc + pc ------------------------------
__global__ void k2_q0(const float* __restrict__ E, const float* __restrict__ Wc)
{
    int b = blockIdx.x, d = threadIdx.x;
    __shared__ float g[Dd];
    float s = 0.f;
    const float* Eb = E + (size_t)b * Nn * Dd + d;
    #pragma unroll 8
    for (int n = 0; n < Nn; n++) s += Eb[n * Dd];
    g[d] = s * (1.0f / Nn);
    __syncthreads();
    float acc = g_pc[d];
    #pragma unroll 8
    for (int k = 0; k < Dd; k++) acc += g[k] * Wc[k * Dd + d];
    g_q0[b * Dd + d] = acc;
}

// ---------------- split kernels: fp32 -> 2x fp16 (to ~2^-22) ----------------
__global__ void k_splitE(const float* __restrict__ E)
{
    const size_t total = (size_t)ROWS_TOTAL * Dd;
    const size_t stride = (size_t)gridDim.x * blockDim.x;
    for (size_t i = (size_t)blockIdx.x * blockDim.x + threadIdx.x; i < total; i += stride) {
        float x = E[i];
        __half h0 = __float2half_rn(x);
        float r = x - __half2float(h0);
        __half h1 = __float2half_rn(r);
        g_Es[0][i] = h0; g_Es[1][i] = h1;
    }
}

__global__ void k_splitW(const float* __restrict__ Wk,
                         const float* __restrict__ Wv,
                         const float* __restrict__ Ws)
{
    const int w = blockIdx.x, n = blockIdx.y, k = threadIdx.x;
    const float* src;
    if      (w == 0) src = Wk;
    else if (w == 1) src = Wv;
    else if (w == 2) src = g_Wlk2;
    else             src = Ws + Dd * Dd;
    float x = src[k * Dd + n] * WSCALE;
    __half h0 = __float2half_rn(x);
    float r = x - __half2float(h0);
    __half h1 = __float2half_rn(r);
    g_Wt[0][w][n * Dd + k] = h0;
    g_Wt[1][w][n * Dd + k] = h1;
}

// ---------------- k3t: mma.sync fp16-2split GEMM, cp.async pipelined --------
__global__ void __launch_bounds__(256, 2) k3t_mma()
{
    extern __shared__ char smem[];
    const uint32_t sbase = smem_u32(smem);
    const int tid = threadIdx.x;
    const int warp = tid >> 5, lane = tid & 31;
    const int rowbase = blockIdx.x * 128;
    const int nbase   = blockIdx.y * 128;
    const int w       = blockIdx.z;

    float* out;
    if      (w == 0) out = g_K;
    else if (w == 1) out = g_V;
    else if (w == 2) out = g_LK2;
    else             out = g_P;

    const int wm = warp & 3;
    const int wn = warp >> 2;

    float acc[2][8][4] = {};

    uint32_t st_dst[8];
    const __half* st_src[8];
    #pragma unroll
    for (int it = 0; it < 8; it++) {
        int i = tid + it * 256;
        int reg = i >> 10, s = (i >> 9) & 1, row = (i >> 2) & 127, q = i & 3;
        uint32_t off = (uint32_t)(s * 8192 + row * 64 + ((q * 16) ^ ((row & 6) << 3)));
        if (reg == 0) {
            st_dst[it] = off;
            st_src[it] = &g_Es[s][(size_t)(rowbase + row) * Dd + q * 8];
        } else {
            st_dst[it] = 32768u + off;
            st_src[it] = &g_Wt[s][w][(size_t)(nbase + row) * Dd + q * 8];
        }
    }

    uint32_t a_off[2], a_mask[2];
    #pragma unroll
    for (int mb = 0; mb < 2; mb++) {
        int row = wm * 32 + mb * 16 + (lane & 15);
        a_off[mb]  = (uint32_t)(row * 64);
        a_mask[mb] = (uint32_t)(((row & 6) << 3) ^ ((lane >> 4) * 16));
    }
    uint32_t b_off[4], b_mask[4];
    #pragma unroll
    for (int p = 0; p < 4; p++) {
        int pr = lane >> 3;
        int nrow = wn * 64 + p * 16 + ((pr >> 1) << 3) + (lane & 7);
        b_off[p]  = (uint32_t)(nrow * 64);
        b_mask[p] = (uint32_t)(((nrow & 6) << 3) ^ ((pr & 1) * 16));
    }

    {
        const uint32_t abase = sbase + K3_ABUF(0);
        #pragma unroll
        for (int it = 0; it < 8; it++)
            cp_async16(abase + st_dst[it], st_src[it]);
        CP_COMMIT();
    }

    for (int c = 0; c < 8; c++) {
        CP_WAIT0();
        __syncthreads();

        if (c + 1 < 8) {
            const uint32_t abase = sbase + K3_ABUF((c + 1) & 1);
            const int kadv = (c + 1) * 32;
            #pragma unroll
            for (int it = 0; it < 8; it++)
                cp_async16(abase + st_dst[it], st_src[it] + kadv);
            CP_COMMIT();
        }

        const uint32_t Ab = sbase + K3_ABUF(c & 1);
        const uint32_t Bb = sbase + K3_BBUF(c & 1);

        #pragma unroll
        for (int ks = 0; ks < 2; ks++) {
            const uint32_t kx = (uint32_t)(ks * 32);
            uint32_t af[2][2][4];
            #pragma unroll
            for (int s = 0; s < 2; s++)
                #pragma unroll
                for (int mb = 0; mb < 2; mb++)
                    ldsm_x4(af[s][mb], Ab + s * 8192 + a_off[mb] + (kx ^ a_mask[mb]));
            #pragma unroll
            for (int p = 0; p < 4; p++) {
                uint32_t b0[4];
                ldsm_x4(b0, Bb + b_off[p] + (kx ^ b_mask[p]));
                #pragma unroll
                for (int sa = 0; sa < 2; sa++) {
                    mma_fp16(acc[0][2 * p],     af[sa][0], b0 + 0);
                    mma_fp16(acc[0][2 * p + 1], af[sa][0], b0 + 2);
                    mma_fp16(acc[1][2 * p],     af[sa][1], b0 + 0);
                    mma_fp16(acc[1][2 * p + 1], af[sa][1], b0 + 2);
                }
                uint32_t b1[4];
                ldsm_x4(b1, Bb + 8192 + b_off[p] + (kx ^ b_mask[p]));
                mma_fp16(acc[0][2 * p],     af[0][0], b1 + 0);
                mma_fp16(acc[0][2 * p + 1], af[0][0], b1 + 2);
                mma_fp16(acc[1][2 * p],     af[0][1], b1 + 0);
                mma_fp16(acc[1][2 * p + 1], af[0][1], b1 + 2);
            }
        }
        __syncthreads();
    }

    const int r0 = rowbase + wm * 32 + (lane >> 2);
    const int c0 = nbase + wn * 64 + (lane & 3) * 2;
    #pragma unroll
    for (int mb = 0; mb < 2; mb++)
        #pragma unroll
        for (int nb = 0; nb < 8; nb++) {
            float2 lo = make_float2(acc[mb][nb][0] * WUNSCALE, acc[mb][nb][1] * WUNSCALE);
            float2 hi = make_float2(acc[mb][nb][2] * WUNSCALE, acc[mb][nb][3] * WUNSCALE);
            *(float2*)(out + (size_t)(r0 + mb * 16)     * Dd + c0 + nb * 8) = lo;
            *(float2*)(out + (size_t)(r0 + mb * 16 + 8) * Dd + c0 + nb * 8) = hi;
        }
}

// ---------------- k4: persistent decode, NB=2 batches per block -------------
struct K4Smem {
    float q[NB][Dd];
    float heads[NB][Dd];
    float cc[NB][Nn][9];
    float pp[NB][Hh][Nn + 4];
    float ls[NB][Nn];
    int   list[NB][Nn];
    float er[NB][Dd];
    float sum[NB][Hh];
    int   sel[NB];
    int   cnt;
};

__device__ __forceinline__ void k4_finalize_q(K4Smem& S, int tid, int mlp,
                                              const float* __restrict__ W1,
                                              const float* __restrict__ b1,
                                              const float* __restrict__ W2,
                                              const float* __restrict__ b2)
{
    if (mlp) {
        __syncthreads();
        float m1[NB];
        #pragma unroll
        for (int bb = 0; bb < NB; bb++) m1[bb] = b1[tid];
        #pragma unroll 8
        for (int k = 0; k < Dd; k++) {
            float wv = W1[k * Dd + tid];
            #pragma unroll
            for (int bb = 0; bb < NB; bb++) m1[bb] += S.q[bb][k] * wv;
        }
        #pragma unroll
        for (int bb = 0; bb < NB; bb++) S.er[bb][tid] = fmaxf(m1[bb], 0.0f);
        __syncthreads();
        float m2[NB];
        #pragma unroll
        for (int bb = 0; bb < NB; bb++) m2[bb] = b2[tid];
        #pragma unroll 8
        for (int k = 0; k < Dd; k++) {
            float wv = W2[k * Dd + tid];
            #pragma unroll
            for (int bb = 0; bb < NB; bb++) m2[bb] += S.er[bb][k] * wv;
        }
        __syncthreads();
        #pragma unroll
        for (int bb = 0; bb < NB; bb++)
            S.q[bb][tid] = (S.q[bb][tid] + m2[bb]) * INV_SQRT_DH;
    } else {
        #pragma unroll
        for (int bb = 0; bb < NB; bb++) S.q[bb][tid] *= INV_SQRT_DH;
    }
    __syncthreads();
}

__global__ void __launch_bounds__(256, 4) k4_decode(const float* __restrict__ E,
                                                    const float* __restrict__ coords,
                                                    const float* __restrict__ Ws,
                                                    const float* __restrict__ W1,
                                                    const float* __restrict__ b1,
                                                    const float* __restrict__ W2,
                                                    const float* __restrict__ b2,
                                                    float* __restrict__ out)
{
    extern __shared__ char smem_raw[];
    K4Smem& S = *(K4Smem*)smem_raw;

    const int b0 = blockIdx.x * NB;
    const int tid = threadIdx.x;
    const int warp = tid >> 5, lane = tid & 31;
    const int wb  = warp >> 2;
    const int wj0 = warp & 3;
    const int mlp = g_mlp;

    if (tid < Nn) {
        #pragma unroll
        for (int bb = 0; bb < NB; bb++) S.list[bb][tid] = tid;
    }
    if (tid == 0) S.cnt = Nn;
    #pragma unroll
    for (int bb = 0; bb < NB; bb++)
        S.q[bb][tid] = g_q0[(b0 + bb) * Dd + tid];
    k4_finalize_q(S, tid, mlp, W1, b1, W2, b2);

    const float* Kbase  = g_K   + (size_t)b0 * Nn * Dd;
    const float* Vbase  = g_V   + (size_t)b0 * Nn * Dd;
    const float* LKbase = g_LK2 + (size_t)b0 * Nn * Dd;

    float ll = 0.f, cost = 0.f;
    float fx = 0.f, fy = 0.f, px = 0.f, py = 0.f;
    float fctx[NB] = {0.f, 0.f};

    for (int t = 0; t < Nn; t++) {
        const int cnt = S.cnt;

        {   // ---- compat: FOUR rows per iteration (8 LDG.128 in flight) ----
            const float4* q4 = (const float4*)S.q[wb];
            float4 qa = q4[lane], qb = q4[lane + 32];
            const float* Kb = Kbase + (size_t)wb * Nn * Dd;
            const int* lst = S.list[wb];
            for (int j = wj0; j < cnt; j += 16) {
                const int j1 = j + 4, j2 = j + 8, j3 = j + 12;
                const bool v1 = (j1 < cnt), v2 = (j2 < cnt), v3 = (j3 < cnt);
                const float4* R0 = (const float4*)(Kb + (size_t)lst[j] * Dd);
                const float4* R1 = (const float4*)(Kb + (size_t)lst[v1 ? j1 : j] * Dd);
                const float4* R2 = (const float4*)(Kb + (size_t)lst[v2 ? j2 : j] * Dd);
                const float4* R3 = (const float4*)(Kb + (size_t)lst[v3 ? j3 : j] * Dd);
                float4 x0 = __ldcg(R0 + lane),      x1 = __ldcg(R0 + lane + 32);
                float4 y0 = __ldcg(R1 + lane),      y1 = __ldcg(R1 + lane + 32);
                float4 z0 = __ldcg(R2 + lane),      z1 = __ldcg(R2 + lane + 32);
                float4 u0 = __ldcg(R3 + lane),      u1 = __ldcg(R3 + lane + 32);
                float alo = DOT4(x0, qa), ahi = DOT4(x1, qb);
                float blo = DOT4(y0, qa), bhi = DOT4(y1, qb);
                float clo = DOT4(z0, qa), chi = DOT4(z1, qb);
                float dlo = DOT4(u0, qa), dhi = DOT4(u1, qb);
                #pragma unroll
                for (int o = 1; o < 8; o <<= 1) {
                    alo += __shfl_xor_sync(0xffffffffu, alo, o);
                    ahi += __shfl_xor_sync(0xffffffffu, ahi, o);
                    blo += __shfl_xor_sync(0xffffffffu, blo, o);
                    bhi += __shfl_xor_sync(0xffffffffu, bhi, o);
                    clo += __shfl_xor_sync(0xffffffffu, clo, o);
                    chi += __shfl_xor_sync(0xffffffffu, chi, o);
                    dlo += __shfl_xor_sync(0xffffffffu, dlo, o);
                    dhi += __shfl_xor_sync(0xffffffffu, dhi, o);
                }
                if ((lane & 7) == 0) {
                    int hg = lane >> 3;
                    S.cc[wb][j][hg]     = alo;
                    S.cc[wb][j][4 + hg] = ahi;
                    if (v1) { S.cc[wb][j1][hg] = blo; S.cc[wb][j1][4 + hg] = bhi; }
                    if (v2) { S.cc[wb][j2][hg] = clo; S.cc[wb][j2][4 + hg] = chi; }
                    if (v3) { S.cc[wb][j3][hg] = dlo; S.cc[wb][j3][4 + hg] = dhi; }
                }
            }
        }
        __syncthreads();

        {   // ---- softmax ----
            const int h = warp;
            #pragma unroll
            for (int bb = 0; bb < NB; bb++) {
                float m = NEGV;
                for (int j = lane; j < cnt; j += 32) m = fmaxf(m, S.cc[bb][j][h]);
                #pragma unroll
                for (int o = 16; o; o >>= 1)
                    m = fmaxf(m, __shfl_xor_sync(0xffffffffu, m, o));
                float s = 0.f;
                for (int j = lane; j < cnt; j += 32) {
                    float e = expf(S.cc[bb][j][h] - m);
                    S.pp[bb][h][j] = e;
                    s += e;
                }
                #pragma unroll
                for (int o = 16; o; o >>= 1) s += __shfl_xor_sync(0xffffffffu, s, o);
                if (lane == 0) S.sum[bb][h] = s;
            }
        }
        __syncthreads();

        {   // ---- heads: 4 accumulators x NB (16 loads in flight) ----------
            const int d = tid, h = tid >> 5;
            float a0[NB] = {0.f, 0.f}, a1[NB] = {0.f, 0.f};
            float a2[NB] = {0.f, 0.f}, a3[NB] = {0.f, 0.f};
            const float* Vd = Vbase + d;
            int j = 0;
            for (; j + 4 <= cnt; j += 4) {
                #pragma unroll
                for (int bb = 0; bb < NB; bb++) {
                    const size_t base = (size_t)bb * Nn;
                    a0[bb] += S.pp[bb][h][j]     * __ldcg(Vd + (base + S.list[bb][j])     * Dd);
                    a1[bb] += S.pp[bb][h][j + 1] * __ldcg(Vd + (base + S.list[bb][j + 1]) * Dd);
                    a2[bb] += S.pp[bb][h][j + 2] * __ldcg(Vd + (base + S.list[bb][j + 2]) * Dd);
                    a3[bb] += S.pp[bb][h][j + 3] * __ldcg(Vd + (base + S.list[bb][j + 3]) * Dd);
                }
            }
            for (; j < cnt; j++) {
                #pragma unroll
                for (int bb = 0; bb < NB; bb++)
                    a0[bb] += S.pp[bb][h][j] *
                              __ldcg(Vd + ((size_t)bb * Nn + S.list[bb][j]) * Dd);
            }
            #pragma unroll
            for (int bb = 0; bb < NB; bb++)
                S.heads[bb][d] = ((a0[bb] + a1[bb]) + (a2[bb] + a3[bb])) / S.sum[bb][h];
        }
        __syncthreads();

        // ---- Woc matvec (registers; overlaps logits phase) ----------------
        float mv0 = 0.f, mv1 = 0.f;
        if (t < Nn - 1) {
            float a0 = 0.f, a1 = 0.f, b0a = 0.f, b1a = 0.f;
            const float* Wp = g_Woc + tid;
            #pragma unroll 8
            for (int k = 0; k < Dd; k += 2) {
                float wv0 = Wp[(size_t)k * Dd];
                float wv1 = Wp[(size_t)(k + 1) * Dd];
                a0  += S.heads[0][k]     * wv0;
                b0a += S.heads[1][k]     * wv0;
                a1  += S.heads[0][k + 1] * wv1;
                b1a += S.heads[1][k + 1] * wv1;
            }
            mv0 = a0 + a1;
            mv1 = b0a + b1a;
        }

        {   // ---- logits: FOUR rows per iteration --------------------------
            const float4* h4 = (const float4*)S.heads[wb];
            float4 ha = h4[lane], hb = h4[lane + 32];
            const float* Lb = LKbase + (size_t)wb * Nn * Dd;
            const int* lst = S.list[wb];
            for (int j = wj0; j < cnt; j += 16) {
                const int j1 = j + 4, j2 = j + 8, j3 = j + 12;
                const bool v1 = (j1 < cnt), v2 = (j2 < cnt), v3 = (j3 < cnt);
                const float4* R0 = (const float4*)(Lb + (size_t)lst[j] * Dd);
                const float4* R1 = (const float4*)(Lb + (size_t)lst[v1 ? j1 : j] * Dd);
                const float4* R2 = (const float4*)(Lb + (size_t)lst[v2 ? j2 : j] * Dd);
                const float4* R3 = (const float4*)(Lb + (size_t)lst[v3 ? j3 : j] * Dd);
                float4 x0 = __ldcg(R0 + lane), x1 = __ldcg(R0 + lane + 32);
                float4 y0 = __ldcg(R1 + lane), y1 = __ldcg(R1 + lane + 32);
                float4 z0 = __ldcg(R2 + lane), z1 = __ldcg(R2 + lane + 32);
                float4 u0 = __ldcg(R3 + lane), u1 = __ldcg(R3 + lane + 32);
                float a = DOT4(x0, ha) + DOT4(x1, hb);
                float b = DOT4(y0, ha) + DOT4(y1, hb);
                float cq = DOT4(z0, ha) + DOT4(z1, hb);
                float dq = DOT4(u0, ha) + DOT4(u1, hb);
                #pragma unroll
                for (int o = 16; o; o >>= 1) {
                    a  += __shfl_xor_sync(0xffffffffu, a, o);
                    b  += __shfl_xor_sync(0xffffffffu, b, o);
                    cq += __shfl_xor_sync(0xffffffffu, cq, o);
                    dq += __shfl_xor_sync(0xffffffffu, dq, o);
                }
                if (lane == 0) {
                    S.ls[wb][j] = CLIPV * tanhf(a * INV_SQRT_D);
                    if (v1) S.ls[wb][j1] = CLIPV * tanhf(b  * INV_SQRT_D);
                    if (v2) S.ls[wb][j2] = CLIPV * tanhf(cq * INV_SQRT_D);
                    if (v3) S.ls[wb][j3] = CLIPV * tanhf(dq * INV_SQRT_D);
                }
            }
        }
        __syncthreads();

        // ---- argmax + log-softmax at selected (warp bb) -------------------
        if (warp < NB) {
            const int bb = warp;
            float m = NEGV; int mj = 0;
            for (int j = lane; j < cnt; j += 32) {
                float v = S.ls[bb][j];
                if (v > m) { m = v; mj = j; }
            }
            #pragma unroll
            for (int o = 16; o; o >>= 1) {
                float vm = __shfl_xor_sync(0xffffffffu, m, o);
                int   vj = __shfl_xor_sync(0xffffffffu, mj, o);
                if (vm > m || (vm == m && vj < mj)) { m = vm; mj = vj; }
            }
            float s = 0.f;
            for (int j = lane; j < cnt; j += 32) s += expf(S.ls[bb][j] - m);
            #pragma unroll
            for (int o = 16; o; o >>= 1) s += __shfl_xor_sync(0xffffffffu, s, o);
            if (lane == 0) {
                int node = S.list[bb][mj];
                S.sel[bb] = node;
                ll += S.ls[bb][mj] - (m + logf(s));
                float cx = coords[((size_t)(b0 + bb) * Nn + node) * 2 + 0];
                float cy = coords[((size_t)(b0 + bb) * Nn + node) * 2 + 1];
                if (t == 0) { fx = cx; fy = cy; }
                else {
                    float dx = cx - px, dy = cy - py;
                    cost += sqrtf(dx * dx + dy * dy);
                }
                px = cx; py = cy;
                S.list[bb][mj] = S.list[bb][cnt - 1];
            }
        }
        if (tid == 0) S.cnt = cnt - 1;
        __syncthreads();

        if (t == 0) {   // fctx[bb] = E[b,first] @ Ws_top
            #pragma unroll
            for (int bb = 0; bb < NB; bb++)
                S.er[bb][tid] =
                    E[((size_t)(b0 + bb) * Nn + S.sel[bb]) * Dd + tid];
            __syncthreads();
            float f[NB] = {0.f, 0.f};
            #pragma unroll 8
            for (int k = 0; k < Dd; k++) {
                float wv = Ws[k * Dd + tid];
                #pragma unroll
                for (int bb = 0; bb < NB; bb++) f[bb] += S.er[bb][k] * wv;
            }
            #pragma unroll
            for (int bb = 0; bb < NB; bb++) fctx[bb] = f[bb];
            __syncthreads();
        }

        if (t < Nn - 1) {   // next raw query: mv + fctx + P[sel]
            float q0v = fctx[0] + mv0 +
                __ldcg(&g_P[((size_t)(b0 + 0) * Nn + S.sel[0]) * Dd + tid]);
            float q1v = fctx[1] + mv1 +
                __ldcg(&g_P[((size_t)(b0 + 1) * Nn + S.sel[1]) * Dd + tid]);
            S.q[0][tid] = q0v;
            S.q[1][tid] = q1v;
            k4_finalize_q(S, tid, mlp, W1, b1, W2, b2);
        }
    }

    if (warp < NB && lane == 0) {
        float dx = px - fx, dy = py - fy;
        cost += sqrtf(dx * dx + dy * dy);
        out[b0 + warp]      = cost;
        out[Bq + b0 + warp] = ll;
    }
}

// ---------------- launcher ---------------------------------------------------
extern "C" void kernel_launch(void* const* d_in, const int* in_sizes, int n_in,
                              void* d_out, int out_size)
{
    const float* coords = (const float*)d_in[0];
    const float* E      = (const float*)d_in[1];
    const float* Wk     = (const float*)d_in[2];
    const float* Wv     = (const float*)d_in[3];
    const float* Wlk    = (const float*)d_in[4];
    const float* Wo     = (const float*)d_in[5];
    const float* Wc     = (const float*)d_in[6];
    const float* Ws     = (const float*)d_in[7];
    const float* Wph    = (const float*)d_in[8];
    const float* W1     = (const float*)d_in[9];
    const float* b1     = (const float*)d_in[10];
    const float* W2     = (const float*)d_in[11];
    const float* b2     = (const float*)d_in[12];
    float* out = (float*)d_out;

    const int k4_smem = (int)sizeof(K4Smem);
    cudaFuncSetAttribute(k4_decode, cudaFuncAttributeMaxDynamicSharedMemorySize,
                         k4_smem);
    cudaFuncSetAttribute(k3t_mma, cudaFuncAttributeMaxDynamicSharedMemorySize,
                         K3T_SMEM);

    k1_weights<<<514, 256>>>(Wo, Wc, Wlk, Ws, Wph, W2, b2);
    k_splitE<<<8192, 256>>>(E);
    {
        dim3 gw(4, 256);
        k_splitW<<<gw, 256>>>(Wk, Wv, Ws);
    }
    {
        dim3 g3(ROWS_TOTAL / 128, 2, 4);
        k3t_mma<<<g3, 256, K3T_SMEM>>>();
    }
    k2_q0<<<Bq, 256>>>(E, Wc);
    k4_decode<<<Bq / NB, 256, k4_smem>>>(E, coords, Ws, W1, b1, W2, b2, out);
}